// round 1
// baseline (speedup 1.0000x reference)
#include <cuda_runtime.h>
#include <math.h>
#include <float.h>

// Problem-fixed dims (GraphAttentionLayer_40673340293481): N=8192, nin=256, nout=128
#define MAXN 8192
#define NIN  256
#define NOUT 128

// Candidate window below global max of hw2. Terms with hw2 < m_i - KEEP have
// softmax weight < e^-60 (reference fp32 weight is 0.0 / denormal there too).
// Rows whose masked max falls below M - (DELTA_CAND - KEEP) are flagged and
// recomputed exactly by the fallback kernel.
#define DELTA_CAND 260.0f
#define KEEP        60.0f

#define CHUNK 2048  // candidate chunk staged per k5 pass (per-row shared weights)

// -------- device scratch (no allocations allowed) --------
__device__ float g_wv2[NIN];
__device__ float g_hw2[MAXN];
__device__ float g_Mthr;               // M - (DELTA_CAND - KEEP)
__device__ int   g_cand_count;
__device__ int   g_cand_idx[MAXN];
__device__ float g_cand_e[MAXN];
__device__ float g_hwC[(size_t)MAXN * NOUT];  // h[cand] @ w
__device__ int   g_flags[MAXN];

// k1: wv2[k] = sum_c w[k,c] * v2[c]   (v2 = v[NOUT:2*NOUT])
__global__ void k1_wv2(const float* __restrict__ w, const float* __restrict__ v) {
    int t = threadIdx.x;  // NIN threads
    float acc = 0.f;
    #pragma unroll 8
    for (int c = 0; c < NOUT; ++c) acc = fmaf(w[t * NOUT + c], v[NOUT + c], acc);
    g_wv2[t] = acc;
}

// k2: hw2[row] = h[row,:] . wv2   (one warp per row)
__global__ void k2_hw2(const float* __restrict__ h, int N) {
    __shared__ float s_wv2[NIN];
    int t = threadIdx.x;  // 256
    s_wv2[t] = g_wv2[t];
    __syncthreads();
    int row = blockIdx.x * 8 + (t >> 5);
    if (row >= N) return;
    int lane = t & 31;
    const float* hr = h + (size_t)row * NIN;
    float acc = 0.f;
    #pragma unroll
    for (int q = 0; q < NIN / 32; ++q)
        acc = fmaf(hr[q * 32 + lane], s_wv2[q * 32 + lane], acc);
    for (int d = 16; d; d >>= 1) acc += __shfl_down_sync(0xffffffffu, acc, d);
    if (lane == 0) g_hw2[row] = acc;
}

// k3: global max of hw2, deterministic candidate compaction, flag clear
__global__ void k3_candidates(int N) {
    __shared__ float s_red[1024];
    __shared__ int   s_wsum[32], s_woff[32];
    int t = threadIdx.x;  // 1024
    int lane = t & 31, wid = t >> 5;

    float lm = -INFINITY;
    for (int j = t; j < N; j += 1024) lm = fmaxf(lm, g_hw2[j]);
    s_red[t] = lm;
    __syncthreads();
    for (int s = 512; s; s >>= 1) {
        if (t < s) s_red[t] = fmaxf(s_red[t], s_red[t + s]);
        __syncthreads();
    }
    float M = s_red[0];
    __syncthreads();
    float thr = M - DELTA_CAND;
    if (t == 0) g_Mthr = M - (DELTA_CAND - KEEP);

    for (int j = t; j < N; j += 1024) g_flags[j] = 0;

    // per-thread contiguous range -> count
    int per = (N + 1023) >> 10;
    int j0 = t * per;
    int c = 0;
    for (int r = 0; r < per; ++r) {
        int j = j0 + r;
        if (j < N && g_hw2[j] >= thr) c++;
    }
    // warp inclusive scan
    int inc = c;
    for (int d = 1; d < 32; d <<= 1) {
        int vv = __shfl_up_sync(0xffffffffu, inc, d);
        if (lane >= d) inc += vv;
    }
    if (lane == 31) s_wsum[wid] = inc;
    __syncthreads();
    if (wid == 0) {
        int vv = s_wsum[lane];
        int winc = vv;
        for (int d = 1; d < 32; d <<= 1) {
            int u = __shfl_up_sync(0xffffffffu, winc, d);
            if (lane >= d) winc += u;
        }
        s_woff[lane] = winc - vv;
        if (lane == 31) g_cand_count = winc;
    }
    __syncthreads();
    int pos = s_woff[wid] + (inc - c);
    for (int r = 0; r < per; ++r) {
        int j = j0 + r;
        if (j < N && g_hw2[j] >= thr) {
            g_cand_idx[pos] = j;
            g_cand_e[pos]   = g_hw2[j];
            pos++;
        }
    }
}

// k4: hwC[k,:] = h[cand_idx[k],:] @ w    (8 candidates per block, 128 threads)
__global__ void k4_hwC(const float* __restrict__ h, const float* __restrict__ w) {
    __shared__ float s_h[8][NIN];
    int cnt = g_cand_count;
    int base = blockIdx.x * 8;
    if (base >= cnt) return;
    int nc = min(8, cnt - base);
    int t = threadIdx.x;  // 128
    for (int cc = 0; cc < nc; ++cc) {
        const float* hr = h + (size_t)g_cand_idx[base + cc] * NIN;
        s_h[cc][t]       = hr[t];
        s_h[cc][t + 128] = hr[t + 128];
    }
    __syncthreads();
    float acc[8] = {0.f, 0.f, 0.f, 0.f, 0.f, 0.f, 0.f, 0.f};
    for (int kk = 0; kk < NIN; ++kk) {
        float wv = w[kk * NOUT + t];
        #pragma unroll
        for (int cc = 0; cc < 8; ++cc) acc[cc] = fmaf(s_h[cc][kk], wv, acc[cc]);
    }
    for (int cc = 0; cc < nc; ++cc)
        g_hwC[(size_t)(base + cc) * NOUT + t] = acc[cc];
}

// k5: main kernel. 4 rows per block, one warp per row. Online softmax over
// candidates; each lane owns 4 output columns (float4).
__global__ void k5_main(const int* __restrict__ adj, float* __restrict__ out, int N) {
    __shared__ float s_w[4][CHUNK];
    int t = threadIdx.x;  // 128
    int r = t >> 5, lane = t & 31;
    int row = blockIdx.x * 4 + r;
    if (row >= N) return;

    const int   cnt  = g_cand_count;
    const float Mthr = g_Mthr;
    const int*  adjrow = adj + (size_t)row * N;
    const float4* hwC4 = (const float4*)g_hwC;  // [cand][NOUT/4]

    float m = -INFINITY, denom = 0.f;
    float4 acc = make_float4(0.f, 0.f, 0.f, 0.f);

    for (int base = 0; base < cnt; base += CHUNK) {
        int nk = min(CHUNK, cnt - base);
        // gather adj for this row's candidates; store masked score
        float lm = -INFINITY;
        for (int k = lane; k < nk; k += 32) {
            int j = g_cand_idx[base + k];
            float e = (adjrow[j] > 0) ? g_cand_e[base + k] : -INFINITY;
            s_w[r][k] = e;
            lm = fmaxf(lm, e);
        }
        for (int d = 16; d; d >>= 1) lm = fmaxf(lm, __shfl_xor_sync(0xffffffffu, lm, d));
        if (lm > m) {
            if (m > -INFINITY) {
                float sc = expf(m - lm);
                acc.x *= sc; acc.y *= sc; acc.z *= sc; acc.w *= sc;
                denom *= sc;
            }
            m = lm;
        }
        __syncwarp();
        if (m > -INFINITY) {
            float thrK = m - KEEP;
            float ls = 0.f;
            for (int k = lane; k < nk; k += 32) {
                float e = s_w[r][k];
                float wgt = (e >= thrK) ? expf(e - m) : 0.f;
                s_w[r][k] = wgt;
                ls += wgt;
            }
            for (int d = 16; d; d >>= 1) ls += __shfl_xor_sync(0xffffffffu, ls, d);
            denom += ls;
            __syncwarp();
            for (int k = 0; k < nk; ++k) {
                float wgt = s_w[r][k];  // broadcast
                float4 hv = hwC4[(size_t)(base + k) * (NOUT / 4) + lane];
                acc.x = fmaf(wgt, hv.x, acc.x);
                acc.y = fmaf(wgt, hv.y, acc.y);
                acc.z = fmaf(wgt, hv.z, acc.z);
                acc.w = fmaf(wgt, hv.w, acc.w);
            }
        }
        __syncwarp();
    }

    bool flag = !(m >= Mthr);  // includes m == -inf
    if (lane == 0) g_flags[row] = flag ? 1 : 0;
    float inv = flag ? 0.f : (1.f / denom);
    float4 o = make_float4(acc.x * inv, acc.y * inv, acc.z * inv, acc.w * inv);
    ((float4*)out)[(size_t)row * (NOUT / 4) + lane] = o;
}

// k6: exact fallback for flagged rows (full adj-row scan, hw rows computed
// on the fly). Statistically never taken; guarantees correctness regardless.
__global__ void k6_fallback(const int* __restrict__ adj, const float* __restrict__ h,
                            const float* __restrict__ w, float* __restrict__ out, int N) {
    int row = blockIdx.x;
    if (!g_flags[row]) return;
    int t = threadIdx.x;  // 128
    __shared__ float s_red[128];
    const int* adjrow = adj + (size_t)row * N;

    float lm = -INFINITY;
    for (int j = t; j < N; j += 128)
        if (adjrow[j] > 0) lm = fmaxf(lm, g_hw2[j]);
    s_red[t] = lm;
    __syncthreads();
    for (int s = 64; s; s >>= 1) {
        if (t < s) s_red[t] = fmaxf(s_red[t], s_red[t + s]);
        __syncthreads();
    }
    float m = s_red[0];
    __syncthreads();
    bool uni = !(m > -INFINITY);  // entire row masked -> uniform softmax

    float acc = 0.f, denom = 0.f;
    __shared__ int   s_list[512];
    __shared__ float s_wl[512];
    __shared__ int   s_cnt;
    __shared__ float s_h[NIN];

    for (int cb = 0; cb < N; cb += 512) {
        if (t == 0) s_cnt = 0;
        __syncthreads();
        int ce = min(cb + 512, N);
        for (int j = cb + t; j < ce; j += 128) {
            bool act = uni ? true : (adjrow[j] > 0 && g_hw2[j] >= m - KEEP);
            if (act) {
                int p = atomicAdd(&s_cnt, 1);
                s_list[p] = j;
                s_wl[p]   = uni ? 1.f : expf(g_hw2[j] - m);
            }
        }
        __syncthreads();
        int L = s_cnt;
        for (int l = 0; l < L; ++l) {
            int j = s_list[l];
            float wl = s_wl[l];
            s_h[t]       = h[(size_t)j * NIN + t];
            s_h[t + 128] = h[(size_t)j * NIN + t + 128];
            __syncthreads();
            float dot = 0.f;
            #pragma unroll 8
            for (int kk = 0; kk < NIN; ++kk)
                dot = fmaf(s_h[kk], w[kk * NOUT + t], dot);
            acc = fmaf(wl, dot, acc);
            denom += wl;
            __syncthreads();
        }
        __syncthreads();
    }
    out[(size_t)row * NOUT + t] = acc / denom;
}

extern "C" void kernel_launch(void* const* d_in, const int* in_sizes, int n_in,
                              void* d_out, int out_size) {
    const float* h   = (const float*)d_in[0];
    const int*   adj = (const int*)d_in[1];
    const float* w   = (const float*)d_in[2];
    const float* v   = (const float*)d_in[3];
    float* out = (float*)d_out;

    int nout = in_sizes[3] / 2;        // 128
    int nin  = in_sizes[2] / nout;     // 256
    int N    = in_sizes[0] / nin;      // 8192
    (void)nout; (void)nin; (void)n_in; (void)out_size;

    k1_wv2<<<1, NIN>>>(w, v);
    k2_hw2<<<(N + 7) / 8, 256>>>(h, N);
    k3_candidates<<<1, 1024>>>(N);
    k4_hwC<<<(N + 7) / 8, 128>>>(h, w);
    k5_main<<<(N + 3) / 4, 128>>>(adj, out, N);
    k6_fallback<<<N, 128>>>(adj, h, w, out, N);
}

// round 2
// speedup vs baseline: 1.5591x; 1.5591x over previous
#include <cuda_runtime.h>
#include <math.h>
#include <float.h>

// Problem-fixed dims: N=8192, nin=256, nout=128
#define MAXN 8192
#define NIN  256
#define NOUT 128

// Candidate window below global max M of hw2. Softmax weights for
// hw2 < m_row - KEEP are < e^-60 (zero in fp32 reference too). Rows whose
// masked max falls below M-(DELTA_CAND-KEEP) are flagged and recomputed
// exactly by k6 (statistically never happens; correctness guarantee only).
#define DELTA_CAND 260.0f
#define KEEP        60.0f

// -------- device scratch (no allocations allowed) --------
__device__ float g_wv2[NIN];
__device__ float g_hw2[MAXN];
__device__ float g_Mthr;
__device__ int   g_cand_count;
__device__ int   g_cand_idx[MAXN];
__device__ float g_cand_e[MAXN];
__device__ float g_hwC[(size_t)MAXN * NOUT];
__device__ int   g_flags[MAXN];

// k1: wv2[k] = w[k,:] . v2   (v2 = v[NOUT:]), also warms w into L2
__global__ void k1_wv2(const float* __restrict__ w, const float* __restrict__ v) {
    int t = threadIdx.x;  // NIN threads
    const float4* wr = (const float4*)(w + (size_t)t * NOUT);
    const float4* v2 = (const float4*)(v + NOUT);
    float a0 = 0.f, a1 = 0.f;
    #pragma unroll 8
    for (int q = 0; q < NOUT / 8; ++q) {
        float4 wa = wr[2 * q], wb = wr[2 * q + 1];
        float4 va = v2[2 * q], vb = v2[2 * q + 1];
        a0 = fmaf(wa.x, va.x, a0); a1 = fmaf(wa.y, va.y, a1);
        a0 = fmaf(wa.z, va.z, a0); a1 = fmaf(wa.w, va.w, a1);
        a0 = fmaf(wb.x, vb.x, a0); a1 = fmaf(wb.y, vb.y, a1);
        a0 = fmaf(wb.z, vb.z, a0); a1 = fmaf(wb.w, vb.w, a1);
    }
    g_wv2[t] = a0 + a1;
}

// k2: hw2[row] = h[row,:] . wv2   (one warp per row, 16 rows/block)
__global__ void k2_hw2(const float* __restrict__ h, int N) {
    __shared__ __align__(16) float s_wv2[NIN];
    int t = threadIdx.x;  // 512
    if (t < NIN) s_wv2[t] = g_wv2[t];
    __syncthreads();
    int row = blockIdx.x * 16 + (t >> 5);
    if (row >= N) return;
    int lane = t & 31;
    const float4* hr = (const float4*)(h + (size_t)row * NIN);
    const float4* wv = (const float4*)s_wv2;
    float4 a = hr[lane], b = hr[lane + 32];
    float4 wa = wv[lane], wb = wv[lane + 32];
    float acc = 0.f;
    acc = fmaf(a.x, wa.x, acc); acc = fmaf(a.y, wa.y, acc);
    acc = fmaf(a.z, wa.z, acc); acc = fmaf(a.w, wa.w, acc);
    acc = fmaf(b.x, wb.x, acc); acc = fmaf(b.y, wb.y, acc);
    acc = fmaf(b.z, wb.z, acc); acc = fmaf(b.w, wb.w, acc);
    for (int d = 16; d; d >>= 1) acc += __shfl_down_sync(0xffffffffu, acc, d);
    if (lane == 0) g_hw2[row] = acc;
}

// k3: global max of hw2, deterministic candidate compaction, flag clear
__global__ void k3_candidates(int N) {
    __shared__ float s_red[1024];
    __shared__ int   s_wsum[32], s_woff[32];
    int t = threadIdx.x;  // 1024
    int lane = t & 31, wid = t >> 5;

    float lm = -INFINITY;
    for (int j = t; j < N; j += 1024) lm = fmaxf(lm, g_hw2[j]);
    s_red[t] = lm;
    __syncthreads();
    for (int s = 512; s; s >>= 1) {
        if (t < s) s_red[t] = fmaxf(s_red[t], s_red[t + s]);
        __syncthreads();
    }
    float M = s_red[0];
    __syncthreads();
    float thr = M - DELTA_CAND;
    if (t == 0) g_Mthr = M - (DELTA_CAND - KEEP);

    for (int j = t; j < N; j += 1024) g_flags[j] = 0;

    int per = (N + 1023) >> 10;
    int j0 = t * per;
    int c = 0;
    for (int r = 0; r < per; ++r) {
        int j = j0 + r;
        if (j < N && g_hw2[j] >= thr) c++;
    }
    int inc = c;
    for (int d = 1; d < 32; d <<= 1) {
        int vv = __shfl_up_sync(0xffffffffu, inc, d);
        if (lane >= d) inc += vv;
    }
    if (lane == 31) s_wsum[wid] = inc;
    __syncthreads();
    if (wid == 0) {
        int vv = s_wsum[lane];
        int winc = vv;
        for (int d = 1; d < 32; d <<= 1) {
            int u = __shfl_up_sync(0xffffffffu, winc, d);
            if (lane >= d) winc += u;
        }
        s_woff[lane] = winc - vv;
        if (lane == 31) g_cand_count = winc;
    }
    __syncthreads();
    int pos = s_woff[wid] + (inc - c);
    for (int r = 0; r < per; ++r) {
        int j = j0 + r;
        if (j < N && g_hw2[j] >= thr) {
            g_cand_idx[pos] = j;
            g_cand_e[pos]   = g_hw2[j];
            pos++;
        }
    }
}

// k4: hwC[c,:] = h[cand_idx[c],:] @ w  — ONE candidate per block, 128 threads.
// All ~cnt working blocks run in parallel on distinct SMs; dual accumulators
// + unroll give pipelined LDS/LDG instead of per-iteration stalls.
__global__ void k4_hwC(const float* __restrict__ h, const float* __restrict__ w) {
    int c = blockIdx.x;
    if (c >= g_cand_count) return;
    __shared__ __align__(16) float s_h[NIN];
    int t = threadIdx.x;  // 128
    const float4* hr = (const float4*)(h + (size_t)g_cand_idx[c] * NIN);
    if (t < NIN / 4) ((float4*)s_h)[t] = hr[t];
    __syncthreads();
    float a0 = 0.f, a1 = 0.f;
    const float* wc = w + t;
    #pragma unroll 8
    for (int kk = 0; kk < NIN; kk += 2) {
        a0 = fmaf(s_h[kk],     wc[(size_t)kk * NOUT],       a0);
        a1 = fmaf(s_h[kk + 1], wc[(size_t)(kk + 1) * NOUT], a1);
    }
    g_hwC[(size_t)c * NOUT + t] = a0 + a1;
}

// k5: main kernel. 8 rows per block (one warp each); candidate idx/e staged
// in shared ONCE per block; zero-weight candidates skipped (warp-uniform).
#define K5_ROWS  8
#define K5_CHUNK 512
__global__ void k5_main(const int* __restrict__ adj, float* __restrict__ out, int N) {
    __shared__ int   s_idx[K5_CHUNK];
    __shared__ float s_e[K5_CHUNK];
    __shared__ float s_w[K5_ROWS][K5_CHUNK];
    int t = threadIdx.x;  // 256
    int r = t >> 5, lane = t & 31;
    int row = blockIdx.x * K5_ROWS + r;

    const int   cnt  = g_cand_count;
    const float Mthr = g_Mthr;
    const int*  adjrow = adj + (size_t)row * N;
    const float4* hwC4 = (const float4*)g_hwC;

    float m = -INFINITY, denom = 0.f;
    float4 acc = make_float4(0.f, 0.f, 0.f, 0.f);

    for (int base = 0; base < cnt; base += K5_CHUNK) {
        int nk = min(K5_CHUNK, cnt - base);
        for (int k = t; k < nk; k += 256) {
            s_idx[k] = g_cand_idx[base + k];
            s_e[k]   = g_cand_e[base + k];
        }
        __syncthreads();

        float lm = -INFINITY;
        for (int k = lane; k < nk; k += 32) {
            int j = s_idx[k];
            float e = (adjrow[j] > 0) ? s_e[k] : -INFINITY;
            s_w[r][k] = e;
            lm = fmaxf(lm, e);
        }
        for (int d = 16; d; d >>= 1) lm = fmaxf(lm, __shfl_xor_sync(0xffffffffu, lm, d));
        if (lm > m) {
            if (m > -INFINITY) {
                float sc = __expf(m - lm);
                acc.x *= sc; acc.y *= sc; acc.z *= sc; acc.w *= sc;
                denom *= sc;
            }
            m = lm;
        }
        __syncwarp();
        if (m > -INFINITY) {
            float thrK = m - KEEP;
            float ls = 0.f;
            for (int k = lane; k < nk; k += 32) {
                float e = s_w[r][k];
                float wgt = (e >= thrK) ? __expf(e - m) : 0.f;
                s_w[r][k] = wgt;
                ls += wgt;
            }
            for (int d = 16; d; d >>= 1) ls += __shfl_xor_sync(0xffffffffu, ls, d);
            denom += ls;
            __syncwarp();
            for (int k = 0; k < nk; ++k) {
                float wgt = s_w[r][k];              // warp-uniform broadcast
                if (wgt != 0.f) {                   // uniform branch: skip masked
                    float4 hv = hwC4[(size_t)(base + k) * (NOUT / 4) + lane];
                    acc.x = fmaf(wgt, hv.x, acc.x);
                    acc.y = fmaf(wgt, hv.y, acc.y);
                    acc.z = fmaf(wgt, hv.z, acc.z);
                    acc.w = fmaf(wgt, hv.w, acc.w);
                }
            }
        }
        __syncthreads();  // protect s_idx/s_e before next chunk reload
    }

    bool flag = !(m >= Mthr);
    if (lane == 0) g_flags[row] = flag ? 1 : 0;
    float inv = flag ? 0.f : (1.f / denom);
    float4 o = make_float4(acc.x * inv, acc.y * inv, acc.z * inv, acc.w * inv);
    ((float4*)out)[(size_t)row * (NOUT / 4) + lane] = o;
}

// k6: exact fallback for flagged rows, grid-stride (statistically dead code).
__global__ void k6_fallback(const int* __restrict__ adj, const float* __restrict__ h,
                            const float* __restrict__ w, float* __restrict__ out, int N) {
    int t = threadIdx.x;  // 128
    __shared__ float s_red[128];
    __shared__ int   s_list[512];
    __shared__ float s_wl[512];
    __shared__ int   s_cnt;
    __shared__ float s_h[NIN];

    for (int row = blockIdx.x; row < N; row += gridDim.x) {
        if (!g_flags[row]) continue;
        const int* adjrow = adj + (size_t)row * N;

        float lm = -INFINITY;
        for (int j = t; j < N; j += 128)
            if (adjrow[j] > 0) lm = fmaxf(lm, g_hw2[j]);
        s_red[t] = lm;
        __syncthreads();
        for (int s = 64; s; s >>= 1) {
            if (t < s) s_red[t] = fmaxf(s_red[t], s_red[t + s]);
            __syncthreads();
        }
        float m = s_red[0];
        __syncthreads();
        bool uni = !(m > -INFINITY);  // fully masked row -> uniform softmax

        float acc = 0.f, denom = 0.f;
        for (int cb = 0; cb < N; cb += 512) {
            if (t == 0) s_cnt = 0;
            __syncthreads();
            int ce = min(cb + 512, N);
            for (int j = cb + t; j < ce; j += 128) {
                bool act = uni ? true : (adjrow[j] > 0 && g_hw2[j] >= m - KEEP);
                if (act) {
                    int p = atomicAdd(&s_cnt, 1);
                    s_list[p] = j;
                    s_wl[p]   = uni ? 1.f : expf(g_hw2[j] - m);
                }
            }
            __syncthreads();
            int L = s_cnt;
            for (int l = 0; l < L; ++l) {
                int j = s_list[l];
                float wl = s_wl[l];
                s_h[t]       = h[(size_t)j * NIN + t];
                s_h[t + 128] = h[(size_t)j * NIN + t + 128];
                __syncthreads();
                float dot = 0.f;
                #pragma unroll 8
                for (int kk = 0; kk < NIN; ++kk)
                    dot = fmaf(s_h[kk], w[kk * NOUT + t], dot);
                acc = fmaf(wl, dot, acc);
                denom += wl;
                __syncthreads();
            }
            __syncthreads();
        }
        out[(size_t)row * NOUT + t] = acc / denom;
        __syncthreads();
    }
}

extern "C" void kernel_launch(void* const* d_in, const int* in_sizes, int n_in,
                              void* d_out, int out_size) {
    const float* h   = (const float*)d_in[0];
    const int*   adj = (const int*)d_in[1];
    const float* w   = (const float*)d_in[2];
    const float* v   = (const float*)d_in[3];
    float* out = (float*)d_out;

    int nout = in_sizes[3] / 2;        // 128
    int nin  = in_sizes[2] / nout;     // 256
    int N    = in_sizes[0] / nin;      // 8192
    (void)nout; (void)nin; (void)n_in; (void)out_size;

    k1_wv2<<<1, NIN>>>(w, v);
    k2_hw2<<<(N + 15) / 16, 512>>>(h, N);
    k3_candidates<<<1, 1024>>>(N);
    k4_hwC<<<MAXN, 128>>>(h, w);
    k5_main<<<(N + K5_ROWS - 1) / K5_ROWS, 256>>>(adj, out, N);
    k6_fallback<<<256, 128>>>(adj, h, w, out, N);
}